// round 1
// baseline (speedup 1.0000x reference)
#include <cuda_runtime.h>

#define TT 50
#define NUSERS 4096
#define NDOCS 50
#define DD 64
#define LU 32
#define ZDIM 128   // 4 * LSTM_UNITS, also FC1 width

// -------- device scratch (no allocations allowed) --------
__device__ float g_P[(NDOCS + 1) * ZDIM];      // precomputed doc-embed @ Wx[0:64] + lstm_b
__device__ float g_dpart[NDOCS * ZDIM];        // doc_feat @ n1_W[64:128] + n1_b
__device__ float g_h[NUSERS * LU];             // final LSTM hidden states

__device__ __forceinline__ float sigf(float x) { return 1.0f / (1.0f + __expf(-x)); }
__device__ __forceinline__ float tanhfast(float x) { return 2.0f / (1.0f + __expf(-2.0f * x)) - 1.0f; }

// ---------------- K0: precompute P and d_part ----------------
__global__ void precompute_kernel(const float* __restrict__ doc_embed,
                                  const float* __restrict__ lstm_Wx,
                                  const float* __restrict__ lstm_b,
                                  const float* __restrict__ doc_prop,
                                  const float* __restrict__ n1_W,
                                  const float* __restrict__ n1_b) {
    int col = threadIdx.x;   // 0..127
    int b = blockIdx.x;      // 0..100
    if (b <= NDOCS) {
        float acc = lstm_b[col];
#pragma unroll 8
        for (int k = 0; k < DD; k++)
            acc = fmaf(doc_embed[b * DD + k], lstm_Wx[k * ZDIM + col], acc);
        g_P[b * ZDIM + col] = acc;
    } else {
        int d = b - (NDOCS + 1);   // 0..49
        float acc = n1_b[col];
#pragma unroll 8
        for (int k = 0; k < DD; k++)
            acc = fmaf(doc_prop[(d + 1) * DD + k], n1_W[(DD + k) * ZDIM + col], acc);
        g_dpart[d * ZDIM + col] = acc;
    }
}

// ---------------- K1: LSTM, warp = user, lane = unit ----------------
__global__ __launch_bounds__(128, 3)
void lstm_kernel(const int* __restrict__ doc_ids,
                 const float* __restrict__ ctime,
                 const float* __restrict__ lstm_Wh,
                 const float* __restrict__ lstm_Wx) {
    const int lane = threadIdx.x & 31;
    const int u = blockIdx.x * 4 + (threadIdx.x >> 5);

    // Wh columns for this lane's 4 gates, cached in registers (128 regs)
    float wh[LU][4];
#pragma unroll
    for (int k = 0; k < LU; k++)
#pragma unroll
        for (int g = 0; g < 4; g++)
            wh[k][g] = lstm_Wh[k * ZDIM + g * 32 + lane];

    float wlast[4];
#pragma unroll
    for (int g = 0; g < 4; g++)
        wlast[g] = lstm_Wx[DD * ZDIM + g * 32 + lane];

    const int* ids = doc_ids + u * TT;
    const float* cts = ctime + u * TT;

    float h = 0.0f, c = 0.0f;
#pragma unroll 1
    for (int t = 0; t < TT; t++) {
        int id = __ldg(&ids[t]);
        float ct = __ldg(&cts[t]);
        const float* Prow = g_P + id * ZDIM;
        float z[4];
#pragma unroll
        for (int g = 0; g < 4; g++)
            z[g] = fmaf(ct, wlast[g], Prow[g * 32 + lane]);
#pragma unroll
        for (int k = 0; k < LU; k++) {
            float hk = __shfl_sync(0xffffffffu, h, k);
#pragma unroll
            for (int g = 0; g < 4; g++)
                z[g] = fmaf(hk, wh[k][g], z[g]);
        }
        float gi = sigf(z[0]);
        float gf = sigf(z[1]);
        float gg = tanhfast(z[2]);
        float go = sigf(z[3]);
        c = fmaf(gf, c, gi * gg);
        h = go * tanhfast(c);
    }
    g_h[u * LU + lane] = h;
}

// ---------------- K2: per-user head + Q-net + slate aggregation ----------------
__global__ __launch_bounds__(256)
void user_kernel(const float* __restrict__ d1_W, const float* __restrict__ d1_b,
                 const float* __restrict__ he_W, const float* __restrict__ he_b,
                 const float* __restrict__ n1_W,
                 const float* __restrict__ n2_W, const float* __restrict__ n2_b,
                 const float* __restrict__ q_W, const float* __restrict__ q_b,
                 const float* __restrict__ doc_prop,
                 const int* __restrict__ slates, int n_slates,
                 float* __restrict__ out) {
    __shared__ float x1s[NDOCS * 129];    // relu(u_part + d_part), padded rows
    __shared__ float w2s[ZDIM * 32];      // n2_W, row-major [k][c]
    __shared__ float ue[DD];
    __shared__ float t1[LU];
    __shared__ float hs[LU];
    __shared__ float ups[ZDIM];
    __shared__ float ss[NDOCS];
    __shared__ float ps[NDOCS];
    __shared__ float qss[NDOCS];
    __shared__ float qw[32];
    __shared__ float n2bs[32];

    const int tid = threadIdx.x;
    const int u = blockIdx.x;

    if (tid < LU) hs[tid] = g_h[u * LU + tid];
    if (tid >= 32 && tid < 64) qw[tid - 32] = q_W[tid - 32];
    if (tid >= 64 && tid < 96) n2bs[tid - 64] = n2_b[tid - 64];
    for (int i = tid; i < ZDIM * 32; i += 256) w2s[i] = n2_W[i];
    __syncthreads();

    // t1 = leaky_relu(h @ d1_W + d1_b)
    if (tid < LU) {
        float acc = d1_b[tid];
#pragma unroll
        for (int k = 0; k < LU; k++) acc = fmaf(hs[k], d1_W[k * LU + tid], acc);
        t1[tid] = acc >= 0.0f ? acc : 0.3f * acc;
    }
    __syncthreads();

    // ue = t1 @ he_W + he_b
    if (tid < DD) {
        float acc = he_b[tid];
#pragma unroll
        for (int k = 0; k < LU; k++) acc = fmaf(t1[k], he_W[k * DD + tid], acc);
        ue[tid] = acc;
    }
    __syncthreads();

    // u_part = ue @ n1_W[0:64]  |  cf -> s = exp(ue . doc_feat)
    if (tid < ZDIM) {
        float acc = 0.0f;
#pragma unroll 8
        for (int k = 0; k < DD; k++) acc = fmaf(ue[k], n1_W[k * ZDIM + tid], acc);
        ups[tid] = acc;
    } else if (tid < ZDIM + NDOCS) {
        int d = tid - ZDIM;
        const float* df = doc_prop + (d + 1) * DD;
        float acc = 0.0f;
#pragma unroll 8
        for (int k = 0; k < DD; k++) acc = fmaf(ue[k], __ldg(&df[k]), acc);
        ss[d] = __expf(acc);
    }
    __syncthreads();

    // x1[d][k] = relu(u_part[k] + d_part[d][k])
    for (int idx = tid; idx < NDOCS * ZDIM; idx += 256) {
        int d = idx >> 7, k = idx & 127;
        float v = ups[k] + g_dpart[idx];
        x1s[d * 129 + k] = v > 0.0f ? v : 0.0f;
    }
    __syncthreads();

    // x2 = relu(x1 @ n2_W + n2_b); qs = x2 . q_W   (4 docs x 4 cols register tile)
    if (tid < 128) {
        const int tx = tid & 7;        // 8 col-threads
        const int ty = tid >> 3;       // 16 doc-threads
        int dr[4];
#pragma unroll
        for (int i = 0; i < 4; i++) dr[i] = min(ty + 16 * i, NDOCS - 1);
        float acc[4][4] = {};
#pragma unroll 4
        for (int k = 0; k < ZDIM; k++) {
            float b0 = w2s[k * 32 + tx];
            float b1 = w2s[k * 32 + tx + 8];
            float b2 = w2s[k * 32 + tx + 16];
            float b3 = w2s[k * 32 + tx + 24];
#pragma unroll
            for (int i = 0; i < 4; i++) {
                float a = x1s[dr[i] * 129 + k];
                acc[i][0] = fmaf(a, b0, acc[i][0]);
                acc[i][1] = fmaf(a, b1, acc[i][1]);
                acc[i][2] = fmaf(a, b2, acc[i][2]);
                acc[i][3] = fmaf(a, b3, acc[i][3]);
            }
        }
#pragma unroll
        for (int i = 0; i < 4; i++) {
            float qp = 0.0f;
#pragma unroll
            for (int j = 0; j < 4; j++) {
                int cc = tx + 8 * j;
                float x2 = fmaxf(acc[i][j] + n2bs[cc], 0.0f);
                qp = fmaf(x2, qw[cc], qp);
            }
            qp += __shfl_xor_sync(0xffffffffu, qp, 1);
            qp += __shfl_xor_sync(0xffffffffu, qp, 2);
            qp += __shfl_xor_sync(0xffffffffu, qp, 4);
            int d = ty + 16 * i;
            if (tx == 0 && d < NDOCS) qss[d] = qp;
        }
    }
    __syncthreads();

    if (tid < NDOCS) ps[tid] = ss[tid] * (qss[tid] + q_b[0]);
    __syncthreads();

    // slate aggregation: out[u][si] = (p_i + p_j) / (s_i + s_j + 1)
    float* orow = out + (size_t)u * (size_t)n_slates;
    for (int si = tid; si < n_slates; si += 256) {
        int i0 = __ldg(&slates[2 * si]);
        int i1 = __ldg(&slates[2 * si + 1]);
        float num = ps[i0] + ps[i1];
        float den = ss[i0] + ss[i1] + 1.0f;
        orow[si] = __fdividef(num, den);
    }
}

extern "C" void kernel_launch(void* const* d_in, const int* in_sizes, int n_in,
                              void* d_out, int out_size) {
    const int*   doc_ids   = (const int*)d_in[0];
    const float* ctime     = (const float*)d_in[1];
    const int*   slates    = (const int*)d_in[2];
    const float* doc_embed = (const float*)d_in[3];
    const float* doc_prop  = (const float*)d_in[4];
    const float* Wx        = (const float*)d_in[5];
    const float* Wh        = (const float*)d_in[6];
    const float* lb        = (const float*)d_in[7];
    const float* d1W       = (const float*)d_in[8];
    const float* d1b       = (const float*)d_in[9];
    const float* heW       = (const float*)d_in[10];
    const float* heb       = (const float*)d_in[11];
    const float* n1W       = (const float*)d_in[12];
    const float* n1b       = (const float*)d_in[13];
    const float* n2W       = (const float*)d_in[14];
    const float* n2b       = (const float*)d_in[15];
    const float* qW        = (const float*)d_in[16];
    const float* qb        = (const float*)d_in[17];
    const int n_slates = in_sizes[2] / 2;

    precompute_kernel<<<2 * NDOCS + 1, ZDIM>>>(doc_embed, Wx, lb, doc_prop, n1W, n1b);
    lstm_kernel<<<NUSERS / 4, 128>>>(doc_ids, ctime, Wh, Wx);
    user_kernel<<<NUSERS, 256>>>(d1W, d1b, heW, heb, n1W, n2W, n2b, qW, qb,
                                 doc_prop, slates, n_slates, (float*)d_out);
}